// round 4
// baseline (speedup 1.0000x reference)
#include <cuda_runtime.h>
#include <cuda_bf16.h>
#include <math.h>
#include <stdint.h>

// ---------------------------------------------------------------------------
// ResGCN15 on GB300 (sm_103 -> HMMA mma.sync bf16 hi/lo split, no tcgen05).
// Uses agg(h@W) == agg(h)@W to fuse relu+bias+residual into the GEMM epilogue
// and keep all activations in bf16 hi/lo split form only.
//   layer1: z = x@W0+b0 (f32); sup = x@W1 (split); x1 = relu(agg(sup)+b1)+z
//   mid l : a = agg(x_l) (split); x_{l+1} = relu(a@W+b) + x_l   (GEMM-fused)
//   final : P = X_cat@W15 (one GEMM over 14 slabs); out = lsm(agg(P)+b15)
// GEMMs are cp.async double-buffered.
// ---------------------------------------------------------------------------

#define MAX_N 50000
#define MAX_E 800000
#define NHID 128
#define NCLASS 40
#define LDK 40          // smem row stride in bf16 elems (32 used + 8 pad = 80B)

#define WOFF_W0   0
#define WOFF_W1   32768
#define WOFF_MID  65536
#define WOFF_W15  278528
#define WT_TOTAL  364544

__device__ __align__(16) int   g_deg[MAX_N];
__device__ __align__(16) int   g_offs[MAX_N + 1];
__device__ __align__(16) int   g_cursor[MAX_N];
__device__ __align__(16) int   g_csr_src[MAX_E];
__device__ __align__(16) float g_csr_w[MAX_E];
__device__ __align__(16) float g_z[(size_t)MAX_N * NHID];
__device__ __align__(16) float g_acc[(size_t)MAX_N * NCLASS];
__device__ __align__(16) __nv_bfloat16 g_wthi[WT_TOTAL];
__device__ __align__(16) __nv_bfloat16 g_wtlo[WT_TOTAL];
__device__ __align__(16) __nv_bfloat16 g_xhi[(size_t)MAX_N * 256];
__device__ __align__(16) __nv_bfloat16 g_xlo[(size_t)MAX_N * 256];
__device__ __align__(16) __nv_bfloat16 g_agghi[(size_t)MAX_N * NHID];
__device__ __align__(16) __nv_bfloat16 g_agglo[(size_t)MAX_N * NHID];
__device__ __align__(16) __nv_bfloat16 g_hhi[(size_t)14 * MAX_N * NHID];
__device__ __align__(16) __nv_bfloat16 g_hlo[(size_t)14 * MAX_N * NHID];

// ---------------------------------------------------------------------------
// helpers
// ---------------------------------------------------------------------------
__device__ __forceinline__ uint32_t s2u(const void* p) {
    return (uint32_t)__cvta_generic_to_shared(p);
}
__device__ __forceinline__ void ldsm4(uint32_t* r, uint32_t addr) {
    asm volatile("ldmatrix.sync.aligned.m8n8.x4.shared.b16 {%0,%1,%2,%3}, [%4];"
                 : "=r"(r[0]), "=r"(r[1]), "=r"(r[2]), "=r"(r[3]) : "r"(addr));
}
__device__ __forceinline__ void mma_bf16(float* d, const uint32_t* a,
                                         uint32_t b0, uint32_t b1) {
    asm volatile(
        "mma.sync.aligned.m16n8k16.row.col.f32.bf16.bf16.f32 "
        "{%0,%1,%2,%3}, {%4,%5,%6,%7}, {%8,%9}, {%0,%1,%2,%3};"
        : "+f"(d[0]), "+f"(d[1]), "+f"(d[2]), "+f"(d[3])
        : "r"(a[0]), "r"(a[1]), "r"(a[2]), "r"(a[3]), "r"(b0), "r"(b1));
}
__device__ __forceinline__ void split1(float v, __nv_bfloat16& h, __nv_bfloat16& l) {
    h = __float2bfloat16(v);
    l = __float2bfloat16(v - __bfloat162float(h));
}
__device__ __forceinline__ uint32_t pack2(float a, float b) {
    __nv_bfloat16 x = __float2bfloat16(a), y = __float2bfloat16(b);
    return (uint32_t)__bfloat16_as_ushort(x) | ((uint32_t)__bfloat16_as_ushort(y) << 16);
}
__device__ __forceinline__ float2 unpack2(uint32_t u) {
    __nv_bfloat162 b;
    *reinterpret_cast<uint32_t*>(&b) = u;
    return __bfloat1622float2(b);
}
__device__ __forceinline__ void cp16(uint32_t saddr, const void* gptr, uint32_t sz) {
    asm volatile("cp.async.cg.shared.global [%0], [%1], 16, %2;"
                 :: "r"(saddr), "l"(gptr), "r"(sz));
}
#define CP_COMMIT() asm volatile("cp.async.commit_group;")

// ---------------------------------------------------------------------------
// CSR build
// ---------------------------------------------------------------------------
__global__ void zero_deg_kernel(int n) {
    int i = blockIdx.x * blockDim.x + threadIdx.x;
    if (i < n) g_deg[i] = 0;
}
__global__ void hist_kernel(const int* __restrict__ dst, int E) {
    int i = blockIdx.x * blockDim.x + threadIdx.x;
    if (i < E) atomicAdd(&g_deg[dst[i]], 1);
}
__global__ void scan_kernel(int n) {
    __shared__ int sums[1024];
    const int t = threadIdx.x;
    const int chunk = (n + 1023) >> 10;
    const int begin = t * chunk;
    const int end = min(begin + chunk, n);
    int s = 0;
    for (int i = begin; i < end; i++) s += g_deg[i];
    sums[t] = s;
    __syncthreads();
    for (int d = 1; d < 1024; d <<= 1) {
        int v = (t >= d) ? sums[t - d] : 0;
        __syncthreads();
        sums[t] += v;
        __syncthreads();
    }
    int run = (t == 0) ? 0 : sums[t - 1];
    if (t == 0) g_offs[0] = 0;
    for (int i = begin; i < end; i++) {
        g_cursor[i] = run;
        run += g_deg[i];
        g_offs[i + 1] = run;
    }
}
__global__ void scatter_kernel(const int* __restrict__ src, const int* __restrict__ dst,
                               const float* __restrict__ w, int E) {
    int i = blockIdx.x * blockDim.x + threadIdx.x;
    if (i < E) {
        int d = dst[i];
        int pos = atomicAdd(&g_cursor[d], 1);
        g_csr_src[pos] = src[i];
        g_csr_w[pos] = w[i];
    }
}

// ---------------------------------------------------------------------------
// prep: split weights (transposed to [n][k]) and x into bf16 hi/lo
// ---------------------------------------------------------------------------
__global__ void split_w_kernel(const float* __restrict__ W0, const float* __restrict__ W1,
                               const float* __restrict__ Wmid, const float* __restrict__ W15) {
    int i = blockIdx.x * blockDim.x + threadIdx.x;
    if (i >= WT_TOTAL) return;
    float v;
    if (i < 32768) {
        int n = i >> 8, k = i & 255;
        v = W0[k * 128 + n];
    } else if (i < 65536) {
        int j = i - 32768;
        int n = j >> 8, k = j & 255;
        v = W1[k * 128 + n];
    } else if (i < 278528) {
        int j = i - 65536;
        int l = j >> 14, jj = j & 16383;
        int n = jj >> 7, k = jj & 127;
        v = Wmid[l * 16384 + k * 128 + n];
    } else {
        int j = i - 278528;
        int n = j / 1792, k = j % 1792;
        v = (n < 40) ? W15[(size_t)k * 40 + n] : 0.f;
    }
    __nv_bfloat16 h, l;
    split1(v, h, l);
    g_wthi[i] = h;
    g_wtlo[i] = l;
}
__global__ void split_x_kernel(const float* __restrict__ x, int total) {
    int i = blockIdx.x * blockDim.x + threadIdx.x;
    if (i >= total) return;
    __nv_bfloat16 h, l;
    split1(x[i], h, l);
    g_xhi[i] = h;
    g_xlo[i] = l;
}

// ---------------------------------------------------------------------------
// Pipelined GEMM: C[M,128] = A[M,K] @ Bt[128,K]^T, bf16 hi/lo 3-MMA split.
// MODE 0: C = acc + bias (fp32 out)
// MODE 1: C = acc        (bf16 split out)
// MODE 2: C = relu(acc + bias) + (reshi+reslo)  (bf16 split out)
// smem: 2 stages x {Ah,Al,Bh,Bl} x 128*LDK bf16
// ---------------------------------------------------------------------------
#define TILE_E (128 * LDK)
#define SMEMSZ_G (2 * 4 * TILE_E * 2)

template<int MODE>
__global__ void __launch_bounds__(256) tgemm_kernel(
    const __nv_bfloat16* __restrict__ Ahi, const __nv_bfloat16* __restrict__ Alo,
    const __nv_bfloat16* __restrict__ Bhi, const __nv_bfloat16* __restrict__ Blo,
    const float* __restrict__ bias, float* __restrict__ Cf,
    const __nv_bfloat16* __restrict__ reshi, const __nv_bfloat16* __restrict__ reslo,
    __nv_bfloat16* __restrict__ outhi, __nv_bfloat16* __restrict__ outlo,
    int M, int K)
{
    extern __shared__ __nv_bfloat16 sb[];
    const int tid = threadIdx.x, lane = tid & 31, wid = tid >> 5;
    const int row0 = blockIdx.x * 128;
    const int wm = wid & 3, wn = wid >> 2;

    float acc[2][8][4];
#pragma unroll
    for (int a = 0; a < 2; a++)
#pragma unroll
        for (int b = 0; b < 8; b++)
#pragma unroll
            for (int c = 0; c < 4; c++) acc[a][b][c] = 0.f;

    const int a_r = (lane & 7) + ((lane >> 3) & 1) * 8;
    const int a_c = (lane >> 4) * 8;
    const int b_r = (lane & 7) + (lane >> 4) * 8;
    const int b_c = ((lane >> 3) & 1) * 8;

    const int nc = K >> 5;

    // stage loader
    auto load_stage = [&](int st, int k0) {
        __nv_bfloat16* sAh = sb + (st * 4 + 0) * TILE_E;
        __nv_bfloat16* sAl = sb + (st * 4 + 1) * TILE_E;
        __nv_bfloat16* sBh = sb + (st * 4 + 2) * TILE_E;
        __nv_bfloat16* sBl = sb + (st * 4 + 3) * TILE_E;
#pragma unroll
        for (int i = tid; i < 512; i += 256) {
            int r = i >> 2, g = i & 3;
            uint32_t sz = (row0 + r < M) ? 16u : 0u;
            size_t go = (size_t)(row0 + r) * K + k0 + g * 8;
            uint32_t so = s2u(sAh + r * LDK + g * 8);
            cp16(so, Ahi + go, sz);
            cp16(s2u(sAl + r * LDK + g * 8), Alo + go, sz);
        }
#pragma unroll
        for (int i = tid; i < 512; i += 256) {
            int r = i >> 2, g = i & 3;
            size_t go = (size_t)r * K + k0 + g * 8;
            cp16(s2u(sBh + r * LDK + g * 8), Bhi + go, 16u);
            cp16(s2u(sBl + r * LDK + g * 8), Blo + go, 16u);
        }
        CP_COMMIT();
    };

    load_stage(0, 0);
    for (int c = 0; c < nc; c++) {
        if (c + 1 < nc) load_stage((c + 1) & 1, (c + 1) << 5);
        if (c + 1 < nc) asm volatile("cp.async.wait_group 1;");
        else            asm volatile("cp.async.wait_group 0;");
        __syncthreads();

        const int st = c & 1;
        const __nv_bfloat16* sAh = sb + (st * 4 + 0) * TILE_E;
        const __nv_bfloat16* sAl = sb + (st * 4 + 1) * TILE_E;
        const __nv_bfloat16* sBh = sb + (st * 4 + 2) * TILE_E;
        const __nv_bfloat16* sBl = sb + (st * 4 + 3) * TILE_E;
#pragma unroll
        for (int k16 = 0; k16 < 32; k16 += 16) {
            uint32_t ah[2][4], al[2][4];
#pragma unroll
            for (int mt = 0; mt < 2; mt++) {
                int er = wm * 32 + mt * 16 + a_r;
                int ec = k16 + a_c;
                ldsm4(ah[mt], s2u(sAh + er * LDK + ec));
                ldsm4(al[mt], s2u(sAl + er * LDK + ec));
            }
#pragma unroll
            for (int p = 0; p < 4; p++) {
                int er = wn * 64 + p * 16 + b_r;
                int ec = k16 + b_c;
                uint32_t bh[4], bl[4];
                ldsm4(bh, s2u(sBh + er * LDK + ec));
                ldsm4(bl, s2u(sBl + er * LDK + ec));
#pragma unroll
                for (int mt = 0; mt < 2; mt++) {
                    mma_bf16(acc[mt][2 * p],     ah[mt], bh[0], bh[1]);
                    mma_bf16(acc[mt][2 * p],     ah[mt], bl[0], bl[1]);
                    mma_bf16(acc[mt][2 * p],     al[mt], bh[0], bh[1]);
                    mma_bf16(acc[mt][2 * p + 1], ah[mt], bh[2], bh[3]);
                    mma_bf16(acc[mt][2 * p + 1], ah[mt], bl[2], bl[3]);
                    mma_bf16(acc[mt][2 * p + 1], al[mt], bh[2], bh[3]);
                }
            }
        }
        __syncthreads();
    }

    // epilogue
    const int er0 = row0 + wm * 32 + (lane >> 2);
    const int ec0 = wn * 64 + (lane & 3) * 2;
#pragma unroll
    for (int mt = 0; mt < 2; mt++) {
#pragma unroll
        for (int nt = 0; nt < 8; nt++) {
            int col = ec0 + nt * 8;
            float bx = 0.f, by = 0.f;
            if (MODE != 1) { bx = bias[col]; by = bias[col + 1]; }
            int r1 = er0 + mt * 16, r2 = r1 + 8;
#pragma unroll
            for (int half = 0; half < 2; half++) {
                int r = half ? r2 : r1;
                float vx = acc[mt][nt][half * 2] + bx;
                float vy = acc[mt][nt][half * 2 + 1] + by;
                if (r >= M) continue;
                size_t o = (size_t)r * 128 + col;
                if (MODE == 0) {
                    *(float2*)(Cf + o) = make_float2(vx, vy);
                } else {
                    if (MODE == 2) {
                        vx = fmaxf(vx, 0.f);
                        vy = fmaxf(vy, 0.f);
                        float2 rh = unpack2(*(const uint32_t*)(reshi + o));
                        float2 rl = unpack2(*(const uint32_t*)(reslo + o));
                        vx += rh.x + rl.x;
                        vy += rh.y + rl.y;
                    }
                    __nv_bfloat16 hx, lx, hy, ly;
                    split1(vx, hx, lx);
                    split1(vy, hy, ly);
                    *(uint32_t*)(outhi + o) =
                        (uint32_t)__bfloat16_as_ushort(hx) | ((uint32_t)__bfloat16_as_ushort(hy) << 16);
                    *(uint32_t*)(outlo + o) =
                        (uint32_t)__bfloat16_as_ushort(lx) | ((uint32_t)__bfloat16_as_ushort(ly) << 16);
                }
            }
        }
    }
}

// ---------------------------------------------------------------------------
// Final GEMM: C[M,40] = X_cat[M,1792] @ W15t[48,1792]^T, pipelined.
// chunk c: k = c*32; slab = 13 - c/4.
// ---------------------------------------------------------------------------
#define BTILE_E (48 * LDK)
#define SMEMSZ_G40 (2 * (2 * TILE_E + 2 * BTILE_E) * 2)

__global__ void __launch_bounds__(256) tgemm40_kernel(
    const __nv_bfloat16* __restrict__ Hhi, const __nv_bfloat16* __restrict__ Hlo,
    const __nv_bfloat16* __restrict__ Bhi, const __nv_bfloat16* __restrict__ Blo,
    float* __restrict__ C, int M)
{
    extern __shared__ __nv_bfloat16 sb[];
    const int tid = threadIdx.x, lane = tid & 31, wid = tid >> 5;
    const int row0 = blockIdx.x * 128;
    const size_t slabE = (size_t)M * 128;
    const int STG = 2 * TILE_E + 2 * BTILE_E;

    float acc[6][4];
#pragma unroll
    for (int a = 0; a < 6; a++)
#pragma unroll
        for (int c = 0; c < 4; c++) acc[a][c] = 0.f;

    const int a_r = (lane & 7) + ((lane >> 3) & 1) * 8;
    const int a_c = (lane >> 4) * 8;
    const int b_r = (lane & 7) + (lane >> 4) * 8;
    const int b_c = ((lane >> 3) & 1) * 8;

    auto load_stage = [&](int st, int c) {
        const int k0g = c * 32;
        const int slab = 13 - (k0g >> 7);
        const int kin = k0g & 127;
        const __nv_bfloat16* Ah = Hhi + (size_t)slab * slabE;
        const __nv_bfloat16* Al = Hlo + (size_t)slab * slabE;
        __nv_bfloat16* sAh = sb + st * STG;
        __nv_bfloat16* sAl = sAh + TILE_E;
        __nv_bfloat16* sBh = sAl + TILE_E;
        __nv_bfloat16* sBl = sBh + BTILE_E;
#pragma unroll
        for (int i = tid; i < 512; i += 256) {
            int r = i >> 2, g = i & 3;
            uint32_t sz = (row0 + r < M) ? 16u : 0u;
            size_t go = (size_t)(row0 + r) * 128 + kin + g * 8;
            cp16(s2u(sAh + r * LDK + g * 8), Ah + go, sz);
            cp16(s2u(sAl + r * LDK + g * 8), Al + go, sz);
        }
        if (tid < 192) {
            int r = tid >> 2, g = tid & 3;
            size_t go = (size_t)r * 1792 + k0g + g * 8;
            cp16(s2u(sBh + r * LDK + g * 8), Bhi + go, 16u);
            cp16(s2u(sBl + r * LDK + g * 8), Blo + go, 16u);
        }
        CP_COMMIT();
    };

    load_stage(0, 0);
    for (int c = 0; c < 56; c++) {
        if (c + 1 < 56) load_stage((c + 1) & 1, c + 1);
        if (c + 1 < 56) asm volatile("cp.async.wait_group 1;");
        else            asm volatile("cp.async.wait_group 0;");
        __syncthreads();

        const int st = c & 1;
        const __nv_bfloat16* sAh = sb + st * STG;
        const __nv_bfloat16* sAl = sAh + TILE_E;
        const __nv_bfloat16* sBh = sAl + TILE_E;
        const __nv_bfloat16* sBl = sBh + BTILE_E;
#pragma unroll
        for (int k16 = 0; k16 < 32; k16 += 16) {
            uint32_t ah[4], al[4];
            int er = wid * 16 + a_r;
            int ec = k16 + a_c;
            ldsm4(ah, s2u(sAh + er * LDK + ec));
            ldsm4(al, s2u(sAl + er * LDK + ec));
#pragma unroll
            for (int p = 0; p < 3; p++) {
                int br = p * 16 + b_r;
                int bc = k16 + b_c;
                uint32_t bh[4], bl[4];
                ldsm4(bh, s2u(sBh + br * LDK + bc));
                ldsm4(bl, s2u(sBl + br * LDK + bc));
                mma_bf16(acc[2 * p],     ah, bh[0], bh[1]);
                mma_bf16(acc[2 * p],     ah, bl[0], bl[1]);
                mma_bf16(acc[2 * p],     al, bh[0], bh[1]);
                mma_bf16(acc[2 * p + 1], ah, bh[2], bh[3]);
                mma_bf16(acc[2 * p + 1], ah, bl[2], bl[3]);
                mma_bf16(acc[2 * p + 1], al, bh[2], bh[3]);
            }
        }
        __syncthreads();
    }
    const int r1 = row0 + wid * 16 + (lane >> 2);
    const int r2 = r1 + 8;
#pragma unroll
    for (int nt = 0; nt < 5; nt++) {
        int col = nt * 8 + (lane & 3) * 2;
        if (r1 < M) *(float2*)(C + (size_t)r1 * 40 + col) =
            make_float2(acc[nt][0], acc[nt][1]);
        if (r2 < M) *(float2*)(C + (size_t)r2 * 40 + col) =
            make_float2(acc[nt][2], acc[nt][3]);
    }
}

// ---------------------------------------------------------------------------
// Aggregation d=128: warp per node, gather from bf16 hi/lo split arrays.
// modeA=1 (layer1): out = relu(agg + bias) + z ; else out = agg. Split write.
// ---------------------------------------------------------------------------
__global__ void __launch_bounds__(256) agg_kernel(
    const __nv_bfloat16* __restrict__ srchi, const __nv_bfloat16* __restrict__ srclo,
    const float* __restrict__ bias, const float* __restrict__ z,
    __nv_bfloat16* __restrict__ outhi, __nv_bfloat16* __restrict__ outlo,
    int n, int modeA)
{
    const int node = (blockIdx.x * blockDim.x + threadIdx.x) >> 5;
    if (node >= n) return;
    const int lane = threadIdx.x & 31;
    const int s = g_offs[node], e = g_offs[node + 1];

    float4 acc = make_float4(0.f, 0.f, 0.f, 0.f);
    int i = s;
    for (; i + 1 < e; i += 2) {
        int s0 = g_csr_src[i], s1 = g_csr_src[i + 1];
        float w0 = g_csr_w[i],  w1 = g_csr_w[i + 1];
        uint2 h0 = *(const uint2*)(srchi + (size_t)s0 * 128 + lane * 4);
        uint2 l0 = *(const uint2*)(srclo + (size_t)s0 * 128 + lane * 4);
        uint2 h1 = *(const uint2*)(srchi + (size_t)s1 * 128 + lane * 4);
        uint2 l1 = *(const uint2*)(srclo + (size_t)s1 * 128 + lane * 4);
        float2 ha = unpack2(h0.x), hb = unpack2(h0.y);
        float2 la = unpack2(l0.x), lb = unpack2(l0.y);
        acc.x = fmaf(w0, ha.x + la.x, acc.x);
        acc.y = fmaf(w0, ha.y + la.y, acc.y);
        acc.z = fmaf(w0, hb.x + lb.x, acc.z);
        acc.w = fmaf(w0, hb.y + lb.y, acc.w);
        ha = unpack2(h1.x); hb = unpack2(h1.y);
        la = unpack2(l1.x); lb = unpack2(l1.y);
        acc.x = fmaf(w1, ha.x + la.x, acc.x);
        acc.y = fmaf(w1, ha.y + la.y, acc.y);
        acc.z = fmaf(w1, hb.x + lb.x, acc.z);
        acc.w = fmaf(w1, hb.y + lb.y, acc.w);
    }
    if (i < e) {
        int s0 = g_csr_src[i];
        float w0 = g_csr_w[i];
        uint2 h0 = *(const uint2*)(srchi + (size_t)s0 * 128 + lane * 4);
        uint2 l0 = *(const uint2*)(srclo + (size_t)s0 * 128 + lane * 4);
        float2 ha = unpack2(h0.x), hb = unpack2(h0.y);
        float2 la = unpack2(l0.x), lb = unpack2(l0.y);
        acc.x = fmaf(w0, ha.x + la.x, acc.x);
        acc.y = fmaf(w0, ha.y + la.y, acc.y);
        acc.z = fmaf(w0, hb.x + lb.x, acc.z);
        acc.w = fmaf(w0, hb.y + lb.y, acc.w);
    }

    if (modeA) {
        float4 b = ((const float4*)bias)[lane];
        float4 r = ((const float4*)z)[(size_t)node * 32 + lane];
        acc.x = fmaxf(acc.x + b.x, 0.f) + r.x;
        acc.y = fmaxf(acc.y + b.y, 0.f) + r.y;
        acc.z = fmaxf(acc.z + b.z, 0.f) + r.z;
        acc.w = fmaxf(acc.w + b.w, 0.f) + r.w;
    }
    __nv_bfloat16 h0, l0, h1, l1, h2, l2, h3, l3;
    split1(acc.x, h0, l0); split1(acc.y, h1, l1);
    split1(acc.z, h2, l2); split1(acc.w, h3, l3);
    uint2 wh, wl;
    wh.x = (uint32_t)__bfloat16_as_ushort(h0) | ((uint32_t)__bfloat16_as_ushort(h1) << 16);
    wh.y = (uint32_t)__bfloat16_as_ushort(h2) | ((uint32_t)__bfloat16_as_ushort(h3) << 16);
    wl.x = (uint32_t)__bfloat16_as_ushort(l0) | ((uint32_t)__bfloat16_as_ushort(l1) << 16);
    wl.y = (uint32_t)__bfloat16_as_ushort(l2) | ((uint32_t)__bfloat16_as_ushort(l3) << 16);
    *(uint2*)(outhi + (size_t)node * 128 + lane * 4) = wh;
    *(uint2*)(outlo + (size_t)node * 128 + lane * 4) = wl;
}

// ---------------------------------------------------------------------------
// Final: agg40 + b15 + log_softmax. Warp per node.
// ---------------------------------------------------------------------------
__global__ void __launch_bounds__(256) spmm40_lsm_kernel(
    const float* __restrict__ accum, const float* __restrict__ b15,
    float* __restrict__ out, int n)
{
    const int node = (blockIdx.x * blockDim.x + threadIdx.x) >> 5;
    if (node >= n) return;
    const int lane = threadIdx.x & 31;
    const int s = g_offs[node], e = g_offs[node + 1];

    float a1 = 0.f, a2 = 0.f;
    for (int i = s; i < e; i++) {
        int src = g_csr_src[i];
        float w = g_csr_w[i];
        const float* row = accum + (size_t)src * 40;
        a1 = fmaf(w, row[lane], a1);
        if (lane < 8) a2 = fmaf(w, row[32 + lane], a2);
    }
    float v1 = a1 + b15[lane];
    float v2 = (lane < 8) ? (a2 + b15[32 + lane]) : -3.0e38f;

    float m = fmaxf(v1, v2);
#pragma unroll
    for (int o = 16; o > 0; o >>= 1) m = fmaxf(m, __shfl_xor_sync(0xffffffffu, m, o));
    float sum = expf(v1 - m) + ((lane < 8) ? expf(v2 - m) : 0.f);
#pragma unroll
    for (int o = 16; o > 0; o >>= 1) sum += __shfl_xor_sync(0xffffffffu, sum, o);
    float ls = m + logf(sum);

    out[(size_t)node * 40 + lane] = v1 - ls;
    if (lane < 8) out[(size_t)node * 40 + 32 + lane] = v2 - ls;
}

// ---------------------------------------------------------------------------
// Launch
// ---------------------------------------------------------------------------
extern "C" void kernel_launch(void* const* d_in, const int* in_sizes, int n_in,
                              void* d_out, int out_size)
{
    const float* x    = (const float*)d_in[0];
    const int*   esrc = (const int*)  d_in[1];
    const int*   edst = (const int*)  d_in[2];
    const float* ew   = (const float*)d_in[3];
    const float* W0   = (const float*)d_in[4];
    const float* b0   = (const float*)d_in[5];
    const float* W1   = (const float*)d_in[6];
    const float* b1   = (const float*)d_in[7];
    const float* Wmid = (const float*)d_in[8];
    const float* bmid = (const float*)d_in[9];
    const float* W15  = (const float*)d_in[10];
    const float* b15  = (const float*)d_in[11];

    const int E = in_sizes[1];
    const int n = in_sizes[0] / 256;
    float* out = (float*)d_out;

    float *z, *accum;
    __nv_bfloat16 *wthi, *wtlo, *xhi, *xlo, *agghi, *agglo, *hhi, *hlo;
    cudaGetSymbolAddress((void**)&z,     g_z);
    cudaGetSymbolAddress((void**)&accum, g_acc);
    cudaGetSymbolAddress((void**)&wthi,  g_wthi);
    cudaGetSymbolAddress((void**)&wtlo,  g_wtlo);
    cudaGetSymbolAddress((void**)&xhi,   g_xhi);
    cudaGetSymbolAddress((void**)&xlo,   g_xlo);
    cudaGetSymbolAddress((void**)&agghi, g_agghi);
    cudaGetSymbolAddress((void**)&agglo, g_agglo);
    cudaGetSymbolAddress((void**)&hhi,   g_hhi);
    cudaGetSymbolAddress((void**)&hlo,   g_hlo);

    cudaFuncSetAttribute(tgemm_kernel<0>, cudaFuncAttributeMaxDynamicSharedMemorySize, SMEMSZ_G);
    cudaFuncSetAttribute(tgemm_kernel<1>, cudaFuncAttributeMaxDynamicSharedMemorySize, SMEMSZ_G);
    cudaFuncSetAttribute(tgemm_kernel<2>, cudaFuncAttributeMaxDynamicSharedMemorySize, SMEMSZ_G);
    cudaFuncSetAttribute(tgemm40_kernel,  cudaFuncAttributeMaxDynamicSharedMemorySize, SMEMSZ_G40);

    const int TB = 256;
    const int gridE = (E + TB - 1) / TB;
    const int gridN = (n + TB - 1) / TB;
    const int gridT = (n + 127) / 128;
    const int gridSpmm = (n + 7) / 8;
    const size_t slab = (size_t)n * 128;

    // 1. CSR build + splits
    zero_deg_kernel<<<gridN, TB>>>(n);
    hist_kernel<<<gridE, TB>>>(edst, E);
    scan_kernel<<<1, 1024>>>(n);
    scatter_kernel<<<gridE, TB>>>(esrc, edst, ew, E);
    split_w_kernel<<<(WT_TOTAL + TB - 1) / TB, TB>>>(W0, W1, Wmid, W15);
    split_x_kernel<<<(n * 256 + TB - 1) / TB, TB>>>(x, n * 256);

    // 2. layer 1: z = x@W0+b0 (f32); sup = x@W1 (split); x1 = relu(agg+b1)+z
    tgemm_kernel<0><<<gridT, 256, SMEMSZ_G>>>(
        xhi, xlo, wthi + WOFF_W0, wtlo + WOFF_W0, b0, z,
        nullptr, nullptr, nullptr, nullptr, n, 256);
    tgemm_kernel<1><<<gridT, 256, SMEMSZ_G>>>(
        xhi, xlo, wthi + WOFF_W1, wtlo + WOFF_W1, nullptr, nullptr,
        nullptr, nullptr, agghi, agglo, n, 256);
    agg_kernel<<<gridSpmm, 256>>>(agghi, agglo, b1, z, hhi, hlo, n, 1);

    // 3. mid layers: a = agg(x_l); x_{l+1} = relu(a@W+b)+x_l (fused in GEMM)
    for (int l = 0; l < 13; l++) {
        agg_kernel<<<gridSpmm, 256>>>(hhi + (size_t)l * slab, hlo + (size_t)l * slab,
                                      nullptr, nullptr, agghi, agglo, n, 0);
        tgemm_kernel<2><<<gridT, 256, SMEMSZ_G>>>(
            agghi, agglo,
            wthi + WOFF_MID + (size_t)l * 16384, wtlo + WOFF_MID + (size_t)l * 16384,
            bmid + (size_t)l * 128, nullptr,
            hhi + (size_t)l * slab, hlo + (size_t)l * slab,
            hhi + (size_t)(l + 1) * slab, hlo + (size_t)(l + 1) * slab, n, 128);
    }

    // 4. P = X_cat @ W15
    tgemm40_kernel<<<gridT, 256, SMEMSZ_G40>>>(hhi, hlo, wthi + WOFF_W15, wtlo + WOFF_W15, accum, n);

    // 5. out = log_softmax(agg(P) + b15)
    spmm40_lsm_kernel<<<gridSpmm, 256>>>(accum, b15, out, n);
}

// round 5
// speedup vs baseline: 1.2887x; 1.2887x over previous
#include <cuda_runtime.h>
#include <cuda_bf16.h>
#include <math.h>
#include <stdint.h>

// ---------------------------------------------------------------------------
// ResGCN15 (sm_103 -> HMMA mma.sync bf16 hi/lo split).
// R3 dataflow (fp32 sup + fp32 gather in agg) + cp.async pipelined GEMMs.
//   layer1: z = x@W0+b0; sup = x@W1; x1 = relu(agg(sup)+b1)+z
//   mid l : sup = x_l@W; x_{l+1} = relu(agg(sup)+b)+x_l (agg epilogue also
//           writes bf16 hi/lo history slab)
//   final : P = X_cat@W15 over 14 slabs (one pipelined GEMM);
//           out = log_softmax(agg40(P)+b15)
// ---------------------------------------------------------------------------

#define MAX_N 50000
#define MAX_E 800000
#define NHID 128
#define NCLASS 40
#define LDK 40          // smem row stride in bf16 (32 + 8 pad = 80B)

#define WOFF_W0   0
#define WOFF_W1   32768
#define WOFF_MID  65536
#define WOFF_W15  278528
#define WT_TOTAL  364544

__device__ __align__(16) int   g_deg[MAX_N];
__device__ __align__(16) int   g_offs[MAX_N + 1];
__device__ __align__(16) int   g_cursor[MAX_N];
__device__ __align__(16) int   g_csr_src[MAX_E];
__device__ __align__(16) float g_csr_w[MAX_E];
__device__ __align__(16) float g_z[(size_t)MAX_N * NHID];
__device__ __align__(16) float g_h[(size_t)MAX_N * NHID];
__device__ __align__(16) float g_sup[(size_t)MAX_N * NHID];
__device__ __align__(16) float g_acc[(size_t)MAX_N * NCLASS];
__device__ __align__(16) __nv_bfloat16 g_wthi[WT_TOTAL];
__device__ __align__(16) __nv_bfloat16 g_wtlo[WT_TOTAL];
__device__ __align__(16) __nv_bfloat16 g_xhi[(size_t)MAX_N * 256];
__device__ __align__(16) __nv_bfloat16 g_xlo[(size_t)MAX_N * 256];
__device__ __align__(16) __nv_bfloat16 g_hhi[(size_t)14 * MAX_N * NHID];
__device__ __align__(16) __nv_bfloat16 g_hlo[(size_t)14 * MAX_N * NHID];

// ---------------------------------------------------------------------------
// helpers
// ---------------------------------------------------------------------------
__device__ __forceinline__ uint32_t s2u(const void* p) {
    return (uint32_t)__cvta_generic_to_shared(p);
}
__device__ __forceinline__ void ldsm4(uint32_t* r, uint32_t addr) {
    asm volatile("ldmatrix.sync.aligned.m8n8.x4.shared.b16 {%0,%1,%2,%3}, [%4];"
                 : "=r"(r[0]), "=r"(r[1]), "=r"(r[2]), "=r"(r[3]) : "r"(addr));
}
__device__ __forceinline__ void mma_bf16(float* d, const uint32_t* a,
                                         uint32_t b0, uint32_t b1) {
    asm volatile(
        "mma.sync.aligned.m16n8k16.row.col.f32.bf16.bf16.f32 "
        "{%0,%1,%2,%3}, {%4,%5,%6,%7}, {%8,%9}, {%0,%1,%2,%3};"
        : "+f"(d[0]), "+f"(d[1]), "+f"(d[2]), "+f"(d[3])
        : "r"(a[0]), "r"(a[1]), "r"(a[2]), "r"(a[3]), "r"(b0), "r"(b1));
}
__device__ __forceinline__ void split1(float v, __nv_bfloat16& h, __nv_bfloat16& l) {
    h = __float2bfloat16(v);
    l = __float2bfloat16(v - __bfloat162float(h));
}
__device__ __forceinline__ void cp16(uint32_t saddr, const void* gptr, uint32_t sz) {
    asm volatile("cp.async.cg.shared.global [%0], [%1], 16, %2;"
                 :: "r"(saddr), "l"(gptr), "r"(sz));
}
#define CP_COMMIT() asm volatile("cp.async.commit_group;")

// ---------------------------------------------------------------------------
// CSR build
// ---------------------------------------------------------------------------
__global__ void zero_deg_kernel(int n) {
    int i = blockIdx.x * blockDim.x + threadIdx.x;
    if (i < n) g_deg[i] = 0;
}
__global__ void hist_kernel(const int* __restrict__ dst, int E) {
    int i = blockIdx.x * blockDim.x + threadIdx.x;
    if (i < E) atomicAdd(&g_deg[dst[i]], 1);
}
__global__ void scan_kernel(int n) {
    __shared__ int sums[1024];
    const int t = threadIdx.x;
    const int chunk = (n + 1023) >> 10;
    const int begin = t * chunk;
    const int end = min(begin + chunk, n);
    int s = 0;
    for (int i = begin; i < end; i++) s += g_deg[i];
    sums[t] = s;
    __syncthreads();
    for (int d = 1; d < 1024; d <<= 1) {
        int v = (t >= d) ? sums[t - d] : 0;
        __syncthreads();
        sums[t] += v;
        __syncthreads();
    }
    int run = (t == 0) ? 0 : sums[t - 1];
    if (t == 0) g_offs[0] = 0;
    for (int i = begin; i < end; i++) {
        g_cursor[i] = run;
        run += g_deg[i];
        g_offs[i + 1] = run;
    }
}
__global__ void scatter_kernel(const int* __restrict__ src, const int* __restrict__ dst,
                               const float* __restrict__ w, int E) {
    int i = blockIdx.x * blockDim.x + threadIdx.x;
    if (i < E) {
        int d = dst[i];
        int pos = atomicAdd(&g_cursor[d], 1);
        g_csr_src[pos] = src[i];
        g_csr_w[pos] = w[i];
    }
}

// ---------------------------------------------------------------------------
// prep: split weights (transposed to [n][k]) and x into bf16 hi/lo
// ---------------------------------------------------------------------------
__global__ void split_w_kernel(const float* __restrict__ W0, const float* __restrict__ W1,
                               const float* __restrict__ Wmid, const float* __restrict__ W15) {
    int i = blockIdx.x * blockDim.x + threadIdx.x;
    if (i >= WT_TOTAL) return;
    float v;
    if (i < 32768) {
        int n = i >> 8, k = i & 255;
        v = W0[k * 128 + n];
    } else if (i < 65536) {
        int j = i - 32768;
        int n = j >> 8, k = j & 255;
        v = W1[k * 128 + n];
    } else if (i < 278528) {
        int j = i - 65536;
        int l = j >> 14, jj = j & 16383;
        int n = jj >> 7, k = jj & 127;
        v = Wmid[l * 16384 + k * 128 + n];
    } else {
        int j = i - 278528;
        int n = j / 1792, k = j % 1792;
        v = (n < 40) ? W15[(size_t)k * 40 + n] : 0.f;
    }
    __nv_bfloat16 h, l;
    split1(v, h, l);
    g_wthi[i] = h;
    g_wtlo[i] = l;
}
__global__ void split_x_kernel(const float* __restrict__ x, int total) {
    int i = blockIdx.x * blockDim.x + threadIdx.x;
    if (i >= total) return;
    __nv_bfloat16 h, l;
    split1(x[i], h, l);
    g_xhi[i] = h;
    g_xlo[i] = l;
}

// ---------------------------------------------------------------------------
// Pipelined GEMM: C[M,128] (fp32) = A[M,K] @ Bt[128,K]^T (+ optional bias).
// bf16 hi/lo 3-MMA split, cp.async double-buffered.
// ---------------------------------------------------------------------------
#define TILE_E (128 * LDK)
#define SMEMSZ_G (2 * 4 * TILE_E * 2)

__global__ void __launch_bounds__(256) tgemm_kernel(
    const __nv_bfloat16* __restrict__ Ahi, const __nv_bfloat16* __restrict__ Alo,
    const __nv_bfloat16* __restrict__ Bhi, const __nv_bfloat16* __restrict__ Blo,
    const float* __restrict__ bias, float* __restrict__ C, int M, int K)
{
    extern __shared__ __nv_bfloat16 sb[];
    const int tid = threadIdx.x, lane = tid & 31, wid = tid >> 5;
    const int row0 = blockIdx.x * 128;
    const int wm = wid & 3, wn = wid >> 2;

    float acc[2][8][4];
#pragma unroll
    for (int a = 0; a < 2; a++)
#pragma unroll
        for (int b = 0; b < 8; b++)
#pragma unroll
            for (int c = 0; c < 4; c++) acc[a][b][c] = 0.f;

    const int a_r = (lane & 7) + ((lane >> 3) & 1) * 8;
    const int a_c = (lane >> 4) * 8;
    const int b_r = (lane & 7) + (lane >> 4) * 8;
    const int b_c = ((lane >> 3) & 1) * 8;
    const int nc = K >> 5;

    auto load_stage = [&](int st, int k0) {
        __nv_bfloat16* sAh = sb + (st * 4 + 0) * TILE_E;
        __nv_bfloat16* sAl = sb + (st * 4 + 1) * TILE_E;
        __nv_bfloat16* sBh = sb + (st * 4 + 2) * TILE_E;
        __nv_bfloat16* sBl = sb + (st * 4 + 3) * TILE_E;
#pragma unroll
        for (int i = tid; i < 512; i += 256) {
            int r = i >> 2, g = i & 3;
            uint32_t sz = (row0 + r < M) ? 16u : 0u;
            size_t go = (size_t)(row0 + r) * K + k0 + g * 8;
            cp16(s2u(sAh + r * LDK + g * 8), Ahi + go, sz);
            cp16(s2u(sAl + r * LDK + g * 8), Alo + go, sz);
        }
#pragma unroll
        for (int i = tid; i < 512; i += 256) {
            int r = i >> 2, g = i & 3;
            size_t go = (size_t)r * K + k0 + g * 8;
            cp16(s2u(sBh + r * LDK + g * 8), Bhi + go, 16u);
            cp16(s2u(sBl + r * LDK + g * 8), Blo + go, 16u);
        }
        CP_COMMIT();
    };

    load_stage(0, 0);
    for (int c = 0; c < nc; c++) {
        if (c + 1 < nc) {
            load_stage((c + 1) & 1, (c + 1) << 5);
            asm volatile("cp.async.wait_group 1;");
        } else {
            asm volatile("cp.async.wait_group 0;");
        }
        __syncthreads();

        const int st = c & 1;
        const __nv_bfloat16* sAh = sb + (st * 4 + 0) * TILE_E;
        const __nv_bfloat16* sAl = sb + (st * 4 + 1) * TILE_E;
        const __nv_bfloat16* sBh = sb + (st * 4 + 2) * TILE_E;
        const __nv_bfloat16* sBl = sb + (st * 4 + 3) * TILE_E;
#pragma unroll
        for (int k16 = 0; k16 < 32; k16 += 16) {
            uint32_t ah[2][4], al[2][4];
#pragma unroll
            for (int mt = 0; mt < 2; mt++) {
                int er = wm * 32 + mt * 16 + a_r;
                int ec = k16 + a_c;
                ldsm4(ah[mt], s2u(sAh + er * LDK + ec));
                ldsm4(al[mt], s2u(sAl + er * LDK + ec));
            }
#pragma unroll
            for (int p = 0; p < 4; p++) {
                int er = wn * 64 + p * 16 + b_r;
                int ec = k16 + b_c;
                uint32_t bh[4], bl[4];
                ldsm4(bh, s2u(sBh + er * LDK + ec));
                ldsm4(bl, s2u(sBl + er * LDK + ec));
#pragma unroll
                for (int mt = 0; mt < 2; mt++) {
                    mma_bf16(acc[mt][2 * p],     ah[mt], bh[0], bh[1]);
                    mma_bf16(acc[mt][2 * p],     ah[mt], bl[0], bl[1]);
                    mma_bf16(acc[mt][2 * p],     al[mt], bh[0], bh[1]);
                    mma_bf16(acc[mt][2 * p + 1], ah[mt], bh[2], bh[3]);
                    mma_bf16(acc[mt][2 * p + 1], ah[mt], bl[2], bl[3]);
                    mma_bf16(acc[mt][2 * p + 1], al[mt], bh[2], bh[3]);
                }
            }
        }
        __syncthreads();
    }

    const int er0 = row0 + wm * 32 + (lane >> 2);
    const int ec0 = wn * 64 + (lane & 3) * 2;
#pragma unroll
    for (int mt = 0; mt < 2; mt++) {
#pragma unroll
        for (int nt = 0; nt < 8; nt++) {
            int col = ec0 + nt * 8;
            float bx = 0.f, by = 0.f;
            if (bias) { bx = bias[col]; by = bias[col + 1]; }
            int r1 = er0 + mt * 16, r2 = r1 + 8;
            if (r1 < M)
                *(float2*)(C + (size_t)r1 * 128 + col) =
                    make_float2(acc[mt][nt][0] + bx, acc[mt][nt][1] + by);
            if (r2 < M)
                *(float2*)(C + (size_t)r2 * 128 + col) =
                    make_float2(acc[mt][nt][2] + bx, acc[mt][nt][3] + by);
        }
    }
}

// ---------------------------------------------------------------------------
// Final GEMM: C[M,40] = X_cat[M,1792] @ W15t[48,1792]^T, pipelined.
// chunk c: k = c*32; slab = 13 - c/4 (reversed concat order).
// ---------------------------------------------------------------------------
#define BTILE_E (48 * LDK)
#define SMEMSZ_G40 (2 * (2 * TILE_E + 2 * BTILE_E) * 2)

__global__ void __launch_bounds__(256) tgemm40_kernel(
    const __nv_bfloat16* __restrict__ Hhi, const __nv_bfloat16* __restrict__ Hlo,
    const __nv_bfloat16* __restrict__ Bhi, const __nv_bfloat16* __restrict__ Blo,
    float* __restrict__ C, int M)
{
    extern __shared__ __nv_bfloat16 sb[];
    const int tid = threadIdx.x, lane = tid & 31, wid = tid >> 5;
    const int row0 = blockIdx.x * 128;
    const size_t slabE = (size_t)M * 128;
    const int STG = 2 * TILE_E + 2 * BTILE_E;

    float acc[6][4];
#pragma unroll
    for (int a = 0; a < 6; a++)
#pragma unroll
        for (int c = 0; c < 4; c++) acc[a][c] = 0.f;

    const int a_r = (lane & 7) + ((lane >> 3) & 1) * 8;
    const int a_c = (lane >> 4) * 8;
    const int b_r = (lane & 7) + (lane >> 4) * 8;
    const int b_c = ((lane >> 3) & 1) * 8;

    auto load_stage = [&](int st, int c) {
        const int k0g = c * 32;
        const int slab = 13 - (k0g >> 7);
        const int kin = k0g & 127;
        const __nv_bfloat16* Ah = Hhi + (size_t)slab * slabE;
        const __nv_bfloat16* Al = Hlo + (size_t)slab * slabE;
        __nv_bfloat16* sAh = sb + st * STG;
        __nv_bfloat16* sAl = sAh + TILE_E;
        __nv_bfloat16* sBh = sAl + TILE_E;
        __nv_bfloat16* sBl = sBh + BTILE_E;
#pragma unroll
        for (int i = tid; i < 512; i += 256) {
            int r = i >> 2, g = i & 3;
            uint32_t sz = (row0 + r < M) ? 16u : 0u;
            size_t go = (size_t)(row0 + r) * 128 + kin + g * 8;
            cp16(s2u(sAh + r * LDK + g * 8), Ah + go, sz);
            cp16(s2u(sAl + r * LDK + g * 8), Al + go, sz);
        }
        if (tid < 192) {
            int r = tid >> 2, g = tid & 3;
            size_t go = (size_t)r * 1792 + k0g + g * 8;
            cp16(s2u(sBh + r * LDK + g * 8), Bhi + go, 16u);
            cp16(s2u(sBl + r * LDK + g * 8), Blo + go, 16u);
        }
        CP_COMMIT();
    };

    load_stage(0, 0);
    for (int c = 0; c < 56; c++) {
        if (c + 1 < 56) {
            load_stage((c + 1) & 1, c + 1);
            asm volatile("cp.async.wait_group 1;");
        } else {
            asm volatile("cp.async.wait_group 0;");
        }
        __syncthreads();

        const int st = c & 1;
        const __nv_bfloat16* sAh = sb + st * STG;
        const __nv_bfloat16* sAl = sAh + TILE_E;
        const __nv_bfloat16* sBh = sAl + TILE_E;
        const __nv_bfloat16* sBl = sBh + BTILE_E;
#pragma unroll
        for (int k16 = 0; k16 < 32; k16 += 16) {
            uint32_t ah[4], al[4];
            int er = wid * 16 + a_r;
            int ec = k16 + a_c;
            ldsm4(ah, s2u(sAh + er * LDK + ec));
            ldsm4(al, s2u(sAl + er * LDK + ec));
#pragma unroll
            for (int p = 0; p < 3; p++) {
                int br = p * 16 + b_r;
                int bc = k16 + b_c;
                uint32_t bh[4], bl[4];
                ldsm4(bh, s2u(sBh + br * LDK + bc));
                ldsm4(bl, s2u(sBl + br * LDK + bc));
                mma_bf16(acc[2 * p],     ah, bh[0], bh[1]);
                mma_bf16(acc[2 * p],     ah, bl[0], bl[1]);
                mma_bf16(acc[2 * p],     al, bh[0], bh[1]);
                mma_bf16(acc[2 * p + 1], ah, bh[2], bh[3]);
                mma_bf16(acc[2 * p + 1], ah, bl[2], bl[3]);
                mma_bf16(acc[2 * p + 1], al, bh[2], bh[3]);
            }
        }
        __syncthreads();
    }
    const int r1 = row0 + wid * 16 + (lane >> 2);
    const int r2 = r1 + 8;
#pragma unroll
    for (int nt = 0; nt < 5; nt++) {
        int col = nt * 8 + (lane & 3) * 2;
        if (r1 < M) *(float2*)(C + (size_t)r1 * 40 + col) =
            make_float2(acc[nt][0], acc[nt][1]);
        if (r2 < M) *(float2*)(C + (size_t)r2 * 40 + col) =
            make_float2(acc[nt][2], acc[nt][3]);
    }
}

// ---------------------------------------------------------------------------
// SpMM d=128: warp per node, fp32 float4 gather. out = relu(agg+bias)+res,
// written fp32 + bf16 hi/lo history. res may alias out.
// ---------------------------------------------------------------------------
__global__ void __launch_bounds__(256) spmm_relu_res_kernel(
    const float* __restrict__ support, const float* __restrict__ bias,
    const float* __restrict__ res, float* __restrict__ out,
    __nv_bfloat16* __restrict__ outhi, __nv_bfloat16* __restrict__ outlo, int n)
{
    const int node = (blockIdx.x * blockDim.x + threadIdx.x) >> 5;
    if (node >= n) return;
    const int lane = threadIdx.x & 31;
    const int s = g_offs[node], e = g_offs[node + 1];
    const float4* sup4 = (const float4*)support;

    float4 acc = make_float4(0.f, 0.f, 0.f, 0.f);
    int i = s;
    for (; i + 1 < e; i += 2) {
        int s0 = g_csr_src[i], s1 = g_csr_src[i + 1];
        float w0 = g_csr_w[i],  w1 = g_csr_w[i + 1];
        float4 v0 = sup4[(size_t)s0 * 32 + lane];
        float4 v1 = sup4[(size_t)s1 * 32 + lane];
        acc.x = fmaf(w0, v0.x, acc.x); acc.y = fmaf(w0, v0.y, acc.y);
        acc.z = fmaf(w0, v0.z, acc.z); acc.w = fmaf(w0, v0.w, acc.w);
        acc.x = fmaf(w1, v1.x, acc.x); acc.y = fmaf(w1, v1.y, acc.y);
        acc.z = fmaf(w1, v1.z, acc.z); acc.w = fmaf(w1, v1.w, acc.w);
    }
    if (i < e) {
        int s0 = g_csr_src[i];
        float w0 = g_csr_w[i];
        float4 v0 = sup4[(size_t)s0 * 32 + lane];
        acc.x = fmaf(w0, v0.x, acc.x); acc.y = fmaf(w0, v0.y, acc.y);
        acc.z = fmaf(w0, v0.z, acc.z); acc.w = fmaf(w0, v0.w, acc.w);
    }
    float4 b = ((const float4*)bias)[lane];
    float4 r = ((const float4*)res)[(size_t)node * 32 + lane];
    float4 o;
    o.x = fmaxf(acc.x + b.x, 0.f) + r.x;
    o.y = fmaxf(acc.y + b.y, 0.f) + r.y;
    o.z = fmaxf(acc.z + b.z, 0.f) + r.z;
    o.w = fmaxf(acc.w + b.w, 0.f) + r.w;
    ((float4*)out)[(size_t)node * 32 + lane] = o;

    __nv_bfloat16 h0, l0, h1, l1, h2, l2, h3, l3;
    split1(o.x, h0, l0); split1(o.y, h1, l1);
    split1(o.z, h2, l2); split1(o.w, h3, l3);
    uint2 wh, wl;
    wh.x = (uint32_t)__bfloat16_as_ushort(h0) | ((uint32_t)__bfloat16_as_ushort(h1) << 16);
    wh.y = (uint32_t)__bfloat16_as_ushort(h2) | ((uint32_t)__bfloat16_as_ushort(h3) << 16);
    wl.x = (uint32_t)__bfloat16_as_ushort(l0) | ((uint32_t)__bfloat16_as_ushort(l1) << 16);
    wl.y = (uint32_t)__bfloat16_as_ushort(l2) | ((uint32_t)__bfloat16_as_ushort(l3) << 16);
    ((uint2*)(outhi + (size_t)node * 128))[lane] = wh;
    ((uint2*)(outlo + (size_t)node * 128))[lane] = wl;
}

// ---------------------------------------------------------------------------
// Final: agg40 + b15 + log_softmax. Warp per node.
// ---------------------------------------------------------------------------
__global__ void __launch_bounds__(256) spmm40_lsm_kernel(
    const float* __restrict__ accum, const float* __restrict__ b15,
    float* __restrict__ out, int n)
{
    const int node = (blockIdx.x * blockDim.x + threadIdx.x) >> 5;
    if (node >= n) return;
    const int lane = threadIdx.x & 31;
    const int s = g_offs[node], e = g_offs[node + 1];

    float a1 = 0.f, a2 = 0.f;
    for (int i = s; i < e; i++) {
        int src = g_csr_src[i];
        float w = g_csr_w[i];
        const float* row = accum + (size_t)src * 40;
        a1 = fmaf(w, row[lane], a1);
        if (lane < 8) a2 = fmaf(w, row[32 + lane], a2);
    }
    float v1 = a1 + b15[lane];
    float v2 = (lane < 8) ? (a2 + b15[32 + lane]) : -3.0e38f;

    float m = fmaxf(v1, v2);
#pragma unroll
    for (int o = 16; o > 0; o >>= 1) m = fmaxf(m, __shfl_xor_sync(0xffffffffu, m, o));
    float sum = expf(v1 - m) + ((lane < 8) ? expf(v2 - m) : 0.f);
#pragma unroll
    for (int o = 16; o > 0; o >>= 1) sum += __shfl_xor_sync(0xffffffffu, sum, o);
    float ls = m + logf(sum);

    out[(size_t)node * 40 + lane] = v1 - ls;
    if (lane < 8) out[(size_t)node * 40 + 32 + lane] = v2 - ls;
}

// ---------------------------------------------------------------------------
// Launch
// ---------------------------------------------------------------------------
extern "C" void kernel_launch(void* const* d_in, const int* in_sizes, int n_in,
                              void* d_out, int out_size)
{
    const float* x    = (const float*)d_in[0];
    const int*   esrc = (const int*)  d_in[1];
    const int*   edst = (const int*)  d_in[2];
    const float* ew   = (const float*)d_in[3];
    const float* W0   = (const float*)d_in[4];
    const float* b0   = (const float*)d_in[5];
    const float* W1   = (const float*)d_in[6];
    const float* b1   = (const float*)d_in[7];
    const float* Wmid = (const float*)d_in[8];
    const float* bmid = (const float*)d_in[9];
    const float* W15  = (const float*)d_in[10];
    const float* b15  = (const float*)d_in[11];

    const int E = in_sizes[1];
    const int n = in_sizes[0] / 256;
    float* out = (float*)d_out;

    float *z, *h, *sup, *accum;
    __nv_bfloat16 *wthi, *wtlo, *xhi, *xlo, *hhi, *hlo;
    cudaGetSymbolAddress((void**)&z,     g_z);
    cudaGetSymbolAddress((void**)&h,     g_h);
    cudaGetSymbolAddress((void**)&sup,   g_sup);
    cudaGetSymbolAddress((void**)&accum, g_acc);
    cudaGetSymbolAddress((void**)&wthi,  g_wthi);
    cudaGetSymbolAddress((void**)&wtlo,  g_wtlo);
    cudaGetSymbolAddress((void**)&xhi,   g_xhi);
    cudaGetSymbolAddress((void**)&xlo,   g_xlo);
    cudaGetSymbolAddress((void**)&hhi,   g_hhi);
    cudaGetSymbolAddress((void**)&hlo,   g_hlo);

    cudaFuncSetAttribute(tgemm_kernel,   cudaFuncAttributeMaxDynamicSharedMemorySize, SMEMSZ_G);
    cudaFuncSetAttribute(tgemm40_kernel, cudaFuncAttributeMaxDynamicSharedMemorySize, SMEMSZ_G40);

    const int TB = 256;
    const int gridE = (E + TB - 1) / TB;
    const int gridN = (n + TB - 1) / TB;
    const int gridT = (n + 127) / 128;
    const int gridSpmm = (n + 7) / 8;
    const size_t slab = (size_t)n * 128;

    // 1. CSR build + splits
    zero_deg_kernel<<<gridN, TB>>>(n);
    hist_kernel<<<gridE, TB>>>(edst, E);
    scan_kernel<<<1, 1024>>>(n);
    scatter_kernel<<<gridE, TB>>>(esrc, edst, ew, E);
    split_w_kernel<<<(WT_TOTAL + TB - 1) / TB, TB>>>(W0, W1, Wmid, W15);
    split_x_kernel<<<(n * 256 + TB - 1) / TB, TB>>>(x, n * 256);

    // 2. layer 1
    tgemm_kernel<<<gridT, 256, SMEMSZ_G>>>(xhi, xlo, wthi + WOFF_W0, wtlo + WOFF_W0, b0, z, n, 256);
    tgemm_kernel<<<gridT, 256, SMEMSZ_G>>>(xhi, xlo, wthi + WOFF_W1, wtlo + WOFF_W1, nullptr, sup, n, 256);
    spmm_relu_res_kernel<<<gridSpmm, 256>>>(sup, b1, z, h, hhi, hlo, n);

    // 3. mid layers
    for (int l = 0; l < 13; l++) {
        tgemm_kernel<<<gridT, 256, SMEMSZ_G>>>(hhi + (size_t)l * slab, hlo + (size_t)l * slab,
                                               wthi + WOFF_MID + (size_t)l * 16384,
                                               wtlo + WOFF_MID + (size_t)l * 16384,
                                               nullptr, sup, n, 128);
        spmm_relu_res_kernel<<<gridSpmm, 256>>>(sup, bmid + (size_t)l * 128, h, h,
                                                hhi + (size_t)(l + 1) * slab,
                                                hlo + (size_t)(l + 1) * slab, n);
    }

    // 4. P = X_cat @ W15
    tgemm40_kernel<<<gridT, 256, SMEMSZ_G40>>>(hhi, hlo, wthi + WOFF_W15, wtlo + WOFF_W15, accum, n);

    // 5. out = log_softmax(agg40(P) + b15)
    spmm40_lsm_kernel<<<gridSpmm, 256>>>(accum, b15, out, n);
}

// round 7
// speedup vs baseline: 1.4242x; 1.1051x over previous
#include <cuda_runtime.h>
#include <cuda_bf16.h>
#include <cuda_fp16.h>
#include <math.h>
#include <stdint.h>

// ---------------------------------------------------------------------------
// ResGCN15 (sm_103 -> HMMA mma.sync bf16 hi/lo split).
// R5 structure + SCALED fp16 "sup" stream: GEMM output feeding aggregation is
// stored as sup*2^-10 in fp16 (halves gather traffic; scaling avoids fp16
// overflow from the network's positive-feedback magnitude growth). The agg
// result is multiplied by 2^10 (exact). Residual path fp32 / bf16-split.
// ---------------------------------------------------------------------------

#define MAX_N 50000
#define MAX_E 800000
#define NHID 128
#define NCLASS 40
#define LDK 40          // smem row stride in bf16 (32 + 8 pad = 80B)

#define SUP_SCALE   0.0009765625f   // 2^-10
#define SUP_UNSCALE 1024.0f         // 2^10

#define WOFF_W0   0
#define WOFF_W1   32768
#define WOFF_MID  65536
#define WOFF_W15  278528
#define WT_TOTAL  364544

__device__ __align__(16) int   g_deg[MAX_N];
__device__ __align__(16) int   g_offs[MAX_N + 1];
__device__ __align__(16) int   g_cursor[MAX_N];
__device__ __align__(16) int   g_csr_src[MAX_E];
__device__ __align__(16) float g_csr_w[MAX_E];
__device__ __align__(16) float g_z[(size_t)MAX_N * NHID];
__device__ __align__(16) float g_h[(size_t)MAX_N * NHID];
__device__ __align__(16) __half g_sup[(size_t)MAX_N * NHID];
__device__ __align__(16) float g_acc[(size_t)MAX_N * NCLASS];
__device__ __align__(16) __nv_bfloat16 g_wthi[WT_TOTAL];
__device__ __align__(16) __nv_bfloat16 g_wtlo[WT_TOTAL];
__device__ __align__(16) __nv_bfloat16 g_xhi[(size_t)MAX_N * 256];
__device__ __align__(16) __nv_bfloat16 g_xlo[(size_t)MAX_N * 256];
__device__ __align__(16) __nv_bfloat16 g_hhi[(size_t)14 * MAX_N * NHID];
__device__ __align__(16) __nv_bfloat16 g_hlo[(size_t)14 * MAX_N * NHID];

// ---------------------------------------------------------------------------
// helpers
// ---------------------------------------------------------------------------
__device__ __forceinline__ uint32_t s2u(const void* p) {
    return (uint32_t)__cvta_generic_to_shared(p);
}
__device__ __forceinline__ void ldsm4(uint32_t* r, uint32_t addr) {
    asm volatile("ldmatrix.sync.aligned.m8n8.x4.shared.b16 {%0,%1,%2,%3}, [%4];"
                 : "=r"(r[0]), "=r"(r[1]), "=r"(r[2]), "=r"(r[3]) : "r"(addr));
}
__device__ __forceinline__ void mma_bf16(float* d, const uint32_t* a,
                                         uint32_t b0, uint32_t b1) {
    asm volatile(
        "mma.sync.aligned.m16n8k16.row.col.f32.bf16.bf16.f32 "
        "{%0,%1,%2,%3}, {%4,%5,%6,%7}, {%8,%9}, {%0,%1,%2,%3};"
        : "+f"(d[0]), "+f"(d[1]), "+f"(d[2]), "+f"(d[3])
        : "r"(a[0]), "r"(a[1]), "r"(a[2]), "r"(a[3]), "r"(b0), "r"(b1));
}
__device__ __forceinline__ void split1(float v, __nv_bfloat16& h, __nv_bfloat16& l) {
    h = __float2bfloat16(v);
    l = __float2bfloat16(v - __bfloat162float(h));
}
__device__ __forceinline__ void cp16(uint32_t saddr, const void* gptr, uint32_t sz) {
    asm volatile("cp.async.cg.shared.global [%0], [%1], 16, %2;"
                 :: "r"(saddr), "l"(gptr), "r"(sz));
}
#define CP_COMMIT() asm volatile("cp.async.commit_group;")

// ---------------------------------------------------------------------------
// CSR build
// ---------------------------------------------------------------------------
__global__ void zero_deg_kernel(int n) {
    int i = blockIdx.x * blockDim.x + threadIdx.x;
    if (i < n) g_deg[i] = 0;
}
__global__ void hist_kernel(const int* __restrict__ dst, int E) {
    int i = blockIdx.x * blockDim.x + threadIdx.x;
    if (i < E) atomicAdd(&g_deg[dst[i]], 1);
}
__global__ void scan_kernel(int n) {
    __shared__ int sums[1024];
    const int t = threadIdx.x;
    const int chunk = (n + 1023) >> 10;
    const int begin = t * chunk;
    const int end = min(begin + chunk, n);
    int s = 0;
    for (int i = begin; i < end; i++) s += g_deg[i];
    sums[t] = s;
    __syncthreads();
    for (int d = 1; d < 1024; d <<= 1) {
        int v = (t >= d) ? sums[t - d] : 0;
        __syncthreads();
        sums[t] += v;
        __syncthreads();
    }
    int run = (t == 0) ? 0 : sums[t - 1];
    if (t == 0) g_offs[0] = 0;
    for (int i = begin; i < end; i++) {
        g_cursor[i] = run;
        run += g_deg[i];
        g_offs[i + 1] = run;
    }
}
__global__ void scatter_kernel(const int* __restrict__ src, const int* __restrict__ dst,
                               const float* __restrict__ w, int E) {
    int i = blockIdx.x * blockDim.x + threadIdx.x;
    if (i < E) {
        int d = dst[i];
        int pos = atomicAdd(&g_cursor[d], 1);
        g_csr_src[pos] = src[i];
        g_csr_w[pos] = w[i];
    }
}

// ---------------------------------------------------------------------------
// prep: split weights (transposed to [n][k]) and x into bf16 hi/lo
// ---------------------------------------------------------------------------
__global__ void split_w_kernel(const float* __restrict__ W0, const float* __restrict__ W1,
                               const float* __restrict__ Wmid, const float* __restrict__ W15) {
    int i = blockIdx.x * blockDim.x + threadIdx.x;
    if (i >= WT_TOTAL) return;
    float v;
    if (i < 32768) {
        int n = i >> 8, k = i & 255;
        v = W0[k * 128 + n];
    } else if (i < 65536) {
        int j = i - 32768;
        int n = j >> 8, k = j & 255;
        v = W1[k * 128 + n];
    } else if (i < 278528) {
        int j = i - 65536;
        int l = j >> 14, jj = j & 16383;
        int n = jj >> 7, k = jj & 127;
        v = Wmid[l * 16384 + k * 128 + n];
    } else {
        int j = i - 278528;
        int n = j / 1792, k = j % 1792;
        v = (n < 40) ? W15[(size_t)k * 40 + n] : 0.f;
    }
    __nv_bfloat16 h, l;
    split1(v, h, l);
    g_wthi[i] = h;
    g_wtlo[i] = l;
}
__global__ void split_x_kernel(const float* __restrict__ x, int total) {
    int i = blockIdx.x * blockDim.x + threadIdx.x;
    if (i >= total) return;
    __nv_bfloat16 h, l;
    split1(x[i], h, l);
    g_xhi[i] = h;
    g_xlo[i] = l;
}

// ---------------------------------------------------------------------------
// Pipelined GEMM: C[M,128] = A[M,K] @ Bt[128,K]^T (+ optional bias).
// bf16 hi/lo 3-MMA split, cp.async double-buffered.
// OUTF16=0: fp32 out (+bias). OUTF16=1: fp16 out scaled by 2^-10 (no bias).
// ---------------------------------------------------------------------------
#define TILE_E (128 * LDK)
#define SMEMSZ_G (2 * 4 * TILE_E * 2)

template<int OUTF16>
__global__ void __launch_bounds__(256) tgemm_kernel(
    const __nv_bfloat16* __restrict__ Ahi, const __nv_bfloat16* __restrict__ Alo,
    const __nv_bfloat16* __restrict__ Bhi, const __nv_bfloat16* __restrict__ Blo,
    const float* __restrict__ bias, void* __restrict__ Cout, int M, int K)
{
    extern __shared__ __nv_bfloat16 sb[];
    const int tid = threadIdx.x, lane = tid & 31, wid = tid >> 5;
    const int row0 = blockIdx.x * 128;
    const int wm = wid & 3, wn = wid >> 2;

    float acc[2][8][4];
#pragma unroll
    for (int a = 0; a < 2; a++)
#pragma unroll
        for (int b = 0; b < 8; b++)
#pragma unroll
            for (int c = 0; c < 4; c++) acc[a][b][c] = 0.f;

    const int a_r = (lane & 7) + ((lane >> 3) & 1) * 8;
    const int a_c = (lane >> 4) * 8;
    const int b_r = (lane & 7) + (lane >> 4) * 8;
    const int b_c = ((lane >> 3) & 1) * 8;
    const int nc = K >> 5;

    auto load_stage = [&](int st, int k0) {
        __nv_bfloat16* sAh = sb + (st * 4 + 0) * TILE_E;
        __nv_bfloat16* sAl = sb + (st * 4 + 1) * TILE_E;
        __nv_bfloat16* sBh = sb + (st * 4 + 2) * TILE_E;
        __nv_bfloat16* sBl = sb + (st * 4 + 3) * TILE_E;
#pragma unroll
        for (int i = tid; i < 512; i += 256) {
            int r = i >> 2, g = i & 3;
            uint32_t sz = (row0 + r < M) ? 16u : 0u;
            size_t go = (size_t)(row0 + r) * K + k0 + g * 8;
            cp16(s2u(sAh + r * LDK + g * 8), Ahi + go, sz);
            cp16(s2u(sAl + r * LDK + g * 8), Alo + go, sz);
        }
#pragma unroll
        for (int i = tid; i < 512; i += 256) {
            int r = i >> 2, g = i & 3;
            size_t go = (size_t)r * K + k0 + g * 8;
            cp16(s2u(sBh + r * LDK + g * 8), Bhi + go, 16u);
            cp16(s2u(sBl + r * LDK + g * 8), Blo + go, 16u);
        }
        CP_COMMIT();
    };

    load_stage(0, 0);
    for (int c = 0; c < nc; c++) {
        if (c + 1 < nc) {
            load_stage((c + 1) & 1, (c + 1) << 5);
            asm volatile("cp.async.wait_group 1;");
        } else {
            asm volatile("cp.async.wait_group 0;");
        }
        __syncthreads();

        const int st = c & 1;
        const __nv_bfloat16* sAh = sb + (st * 4 + 0) * TILE_E;
        const __nv_bfloat16* sAl = sb + (st * 4 + 1) * TILE_E;
        const __nv_bfloat16* sBh = sb + (st * 4 + 2) * TILE_E;
        const __nv_bfloat16* sBl = sb + (st * 4 + 3) * TILE_E;
#pragma unroll
        for (int k16 = 0; k16 < 32; k16 += 16) {
            uint32_t ah[2][4], al[2][4];
#pragma unroll
            for (int mt = 0; mt < 2; mt++) {
                int er = wm * 32 + mt * 16 + a_r;
                int ec = k16 + a_c;
                ldsm4(ah[mt], s2u(sAh + er * LDK + ec));
                ldsm4(al[mt], s2u(sAl + er * LDK + ec));
            }
#pragma unroll
            for (int p = 0; p < 4; p++) {
                int er = wn * 64 + p * 16 + b_r;
                int ec = k16 + b_c;
                uint32_t bh[4], bl[4];
                ldsm4(bh, s2u(sBh + er * LDK + ec));
                ldsm4(bl, s2u(sBl + er * LDK + ec));
#pragma unroll
                for (int mt = 0; mt < 2; mt++) {
                    mma_bf16(acc[mt][2 * p],     ah[mt], bh[0], bh[1]);
                    mma_bf16(acc[mt][2 * p],     ah[mt], bl[0], bl[1]);
                    mma_bf16(acc[mt][2 * p],     al[mt], bh[0], bh[1]);
                    mma_bf16(acc[mt][2 * p + 1], ah[mt], bh[2], bh[3]);
                    mma_bf16(acc[mt][2 * p + 1], ah[mt], bl[2], bl[3]);
                    mma_bf16(acc[mt][2 * p + 1], al[mt], bh[2], bh[3]);
                }
            }
        }
        __syncthreads();
    }

    const int er0 = row0 + wm * 32 + (lane >> 2);
    const int ec0 = wn * 64 + (lane & 3) * 2;
#pragma unroll
    for (int mt = 0; mt < 2; mt++) {
#pragma unroll
        for (int nt = 0; nt < 8; nt++) {
            int col = ec0 + nt * 8;
            float bx = 0.f, by = 0.f;
            if (!OUTF16 && bias) { bx = bias[col]; by = bias[col + 1]; }
            int r1 = er0 + mt * 16, r2 = r1 + 8;
#pragma unroll
            for (int half = 0; half < 2; half++) {
                int r = half ? r2 : r1;
                if (r >= M) continue;
                float vx = acc[mt][nt][half * 2] + bx;
                float vy = acc[mt][nt][half * 2 + 1] + by;
                if (OUTF16) {
                    __half2* C = (__half2*)Cout;
                    C[((size_t)r * 128 + col) >> 1] =
                        __floats2half2_rn(vx * SUP_SCALE, vy * SUP_SCALE);
                } else {
                    float* C = (float*)Cout;
                    *(float2*)(C + (size_t)r * 128 + col) = make_float2(vx, vy);
                }
            }
        }
    }
}

// ---------------------------------------------------------------------------
// Final GEMM: C[M,40] = X_cat[M,1792] @ W15t[48,1792]^T, pipelined.
// ---------------------------------------------------------------------------
#define BTILE_E (48 * LDK)
#define SMEMSZ_G40 (2 * (2 * TILE_E + 2 * BTILE_E) * 2)

__global__ void __launch_bounds__(256) tgemm40_kernel(
    const __nv_bfloat16* __restrict__ Hhi, const __nv_bfloat16* __restrict__ Hlo,
    const __nv_bfloat16* __restrict__ Bhi, const __nv_bfloat16* __restrict__ Blo,
    float* __restrict__ C, int M)
{
    extern __shared__ __nv_bfloat16 sb[];
    const int tid = threadIdx.x, lane = tid & 31, wid = tid >> 5;
    const int row0 = blockIdx.x * 128;
    const size_t slabE = (size_t)M * 128;
    const int STG = 2 * TILE_E + 2 * BTILE_E;

    float acc[6][4];
#pragma unroll
    for (int a = 0; a < 6; a++)
#pragma unroll
        for (int c = 0; c < 4; c++) acc[a][c] = 0.f;

    const int a_r = (lane & 7) + ((lane >> 3) & 1) * 8;
    const int a_c = (lane >> 4) * 8;
    const int b_r = (lane & 7) + (lane >> 4) * 8;
    const int b_c = ((lane >> 3) & 1) * 8;

    auto load_stage = [&](int st, int c) {
        const int k0g = c * 32;
        const int slab = 13 - (k0g >> 7);
        const int kin = k0g & 127;
        const __nv_bfloat16* Ah = Hhi + (size_t)slab * slabE;
        const __nv_bfloat16* Al = Hlo + (size_t)slab * slabE;
        __nv_bfloat16* sAh = sb + st * STG;
        __nv_bfloat16* sAl = sAh + TILE_E;
        __nv_bfloat16* sBh = sAl + TILE_E;
        __nv_bfloat16* sBl = sBh + BTILE_E;
#pragma unroll
        for (int i = tid; i < 512; i += 256) {
            int r = i >> 2, g = i & 3;
            uint32_t sz = (row0 + r < M) ? 16u : 0u;
            size_t go = (size_t)(row0 + r) * 128 + kin + g * 8;
            cp16(s2u(sAh + r * LDK + g * 8), Ah + go, sz);
            cp16(s2u(sAl + r * LDK + g * 8), Al + go, sz);
        }
        if (tid < 192) {
            int r = tid >> 2, g = tid & 3;
            size_t go = (size_t)r * 1792 + k0g + g * 8;
            cp16(s2u(sBh + r * LDK + g * 8), Bhi + go, 16u);
            cp16(s2u(sBl + r * LDK + g * 8), Blo + go, 16u);
        }
        CP_COMMIT();
    };

    load_stage(0, 0);
    for (int c = 0; c < 56; c++) {
        if (c + 1 < 56) {
            load_stage((c + 1) & 1, c + 1);
            asm volatile("cp.async.wait_group 1;");
        } else {
            asm volatile("cp.async.wait_group 0;");
        }
        __syncthreads();

        const int st = c & 1;
        const __nv_bfloat16* sAh = sb + st * STG;
        const __nv_bfloat16* sAl = sAh + TILE_E;
        const __nv_bfloat16* sBh = sAl + TILE_E;
        const __nv_bfloat16* sBl = sBh + BTILE_E;
#pragma unroll
        for (int k16 = 0; k16 < 32; k16 += 16) {
            uint32_t ah[4], al[4];
            int er = wid * 16 + a_r;
            int ec = k16 + a_c;
            ldsm4(ah, s2u(sAh + er * LDK + ec));
            ldsm4(al, s2u(sAl + er * LDK + ec));
#pragma unroll
            for (int p = 0; p < 3; p++) {
                int br = p * 16 + b_r;
                int bc = k16 + b_c;
                uint32_t bh[4], bl[4];
                ldsm4(bh, s2u(sBh + br * LDK + bc));
                ldsm4(bl, s2u(sBl + br * LDK + bc));
                mma_bf16(acc[2 * p],     ah, bh[0], bh[1]);
                mma_bf16(acc[2 * p],     ah, bl[0], bl[1]);
                mma_bf16(acc[2 * p],     al, bh[0], bh[1]);
                mma_bf16(acc[2 * p + 1], ah, bh[2], bh[3]);
                mma_bf16(acc[2 * p + 1], ah, bl[2], bl[3]);
                mma_bf16(acc[2 * p + 1], al, bh[2], bh[3]);
            }
        }
        __syncthreads();
    }
    const int r1 = row0 + wid * 16 + (lane >> 2);
    const int r2 = r1 + 8;
#pragma unroll
    for (int nt = 0; nt < 5; nt++) {
        int col = nt * 8 + (lane & 3) * 2;
        if (r1 < M) *(float2*)(C + (size_t)r1 * 40 + col) =
            make_float2(acc[nt][0], acc[nt][1]);
        if (r2 < M) *(float2*)(C + (size_t)r2 * 40 + col) =
            make_float2(acc[nt][2], acc[nt][3]);
    }
}

// ---------------------------------------------------------------------------
// SpMM d=128: warp per node, scaled-fp16 gather (8B/lane/edge).
// out = relu(agg*2^10 + bias) + res (fp32) + bf16 hi/lo history write.
// ---------------------------------------------------------------------------
__global__ void __launch_bounds__(256) spmm_relu_res_kernel(
    const __half* __restrict__ support, const float* __restrict__ bias,
    const float* __restrict__ res, float* __restrict__ out,
    __nv_bfloat16* __restrict__ outhi, __nv_bfloat16* __restrict__ outlo, int n)
{
    const int node = (blockIdx.x * blockDim.x + threadIdx.x) >> 5;
    if (node >= n) return;
    const int lane = threadIdx.x & 31;
    const int s = g_offs[node], e = g_offs[node + 1];
    const uint2* sup2 = (const uint2*)support;   // 4 halves per lane

    float4 acc = make_float4(0.f, 0.f, 0.f, 0.f);
    int i = s;
    for (; i + 1 < e; i += 2) {
        int s0 = g_csr_src[i], s1 = g_csr_src[i + 1];
        float w0 = g_csr_w[i],  w1 = g_csr_w[i + 1];
        uint2 u0 = sup2[(size_t)s0 * 32 + lane];
        uint2 u1 = sup2[(size_t)s1 * 32 + lane];
        float2 a0 = __half22float2(*(const __half2*)&u0.x);
        float2 a1 = __half22float2(*(const __half2*)&u0.y);
        acc.x = fmaf(w0, a0.x, acc.x); acc.y = fmaf(w0, a0.y, acc.y);
        acc.z = fmaf(w0, a1.x, acc.z); acc.w = fmaf(w0, a1.y, acc.w);
        float2 b0 = __half22float2(*(const __half2*)&u1.x);
        float2 b1 = __half22float2(*(const __half2*)&u1.y);
        acc.x = fmaf(w1, b0.x, acc.x); acc.y = fmaf(w1, b0.y, acc.y);
        acc.z = fmaf(w1, b1.x, acc.z); acc.w = fmaf(w1, b1.y, acc.w);
    }
    if (i < e) {
        int s0 = g_csr_src[i];
        float w0 = g_csr_w[i];
        uint2 u0 = sup2[(size_t)s0 * 32 + lane];
        float2 a0 = __half22float2(*(const __half2*)&u0.x);
        float2 a1 = __half22float2(*(const __half2*)&u0.y);
        acc.x = fmaf(w0, a0.x, acc.x); acc.y = fmaf(w0, a0.y, acc.y);
        acc.z = fmaf(w0, a1.x, acc.z); acc.w = fmaf(w0, a1.y, acc.w);
    }
    // undo the 2^-10 storage scale (exact)
    acc.x *= SUP_UNSCALE; acc.y *= SUP_UNSCALE;
    acc.z *= SUP_UNSCALE; acc.w *= SUP_UNSCALE;

    float4 b = ((const float4*)bias)[lane];
    float4 r = ((const float4*)res)[(size_t)node * 32 + lane];
    float4 o;
    o.x = fmaxf(acc.x + b.x, 0.f) + r.x;
    o.y = fmaxf(acc.y + b.y, 0.f) + r.y;
    o.z = fmaxf(acc.z + b.z, 0.f) + r.z;
    o.w = fmaxf(acc.w + b.w, 0.f) + r.w;
    ((float4*)out)[(size_t)node * 32 + lane] = o;

    __nv_bfloat16 h0, l0, h1, l1, h2, l2, h3, l3;
    split1(o.x, h0, l0); split1(o.y, h1, l1);
    split1(o.z, h2, l2); split1(o.w, h3, l3);
    uint2 wh, wl;
    wh.x = (uint32_t)__bfloat16_as_ushort(h0) | ((uint32_t)__bfloat16_as_ushort(h1) << 16);
    wh.y = (uint32_t)__bfloat16_as_ushort(h2) | ((uint32_t)__bfloat16_as_ushort(h3) << 16);
    wl.x = (uint32_t)__bfloat16_as_ushort(l0) | ((uint32_t)__bfloat16_as_ushort(l1) << 16);
    wl.y = (uint32_t)__bfloat16_as_ushort(l2) | ((uint32_t)__bfloat16_as_ushort(l3) << 16);
    ((uint2*)(outhi + (size_t)node * 128))[lane] = wh;
    ((uint2*)(outlo + (size_t)node * 128))[lane] = wl;
}

// ---------------------------------------------------------------------------
// Final: agg40 + b15 + log_softmax. Warp per node. fp32 gather (precision).
// ---------------------------------------------------------------------------
__global__ void __launch_bounds__(256) spmm40_lsm_kernel(
    const float* __restrict__ accum, const float* __restrict__ b15,
    float* __restrict__ out, int n)
{
    const int node = (blockIdx.x * blockDim.x + threadIdx.x) >> 5;
    if (node >= n) return;
    const int lane = threadIdx.x & 31;
    const int s = g_offs[node], e = g_offs[node + 1];

    float a1 = 0.f, a2 = 0.f;
    for (int i = s; i < e; i++) {
        int src = g_csr_src[i];
        float w = g_csr_w[i];
        const float* row = accum + (size_t)src * 40;
        a1 = fmaf(w, row[lane], a1);
        if (lane < 8) a2 = fmaf(w, row[32 + lane], a2);
    }
    float v1 = a1 + b15[lane];
    float v2 = (lane < 8) ? (a2 + b15[32 + lane]) : -3.0e38f;

    float m = fmaxf(v1, v2);
#pragma unroll
    for (int o = 16; o > 0; o >>= 1) m = fmaxf(m, __shfl_xor_sync(0xffffffffu, m, o));
    float sum = expf(v1 - m) + ((lane < 8) ? expf(v2 - m) : 0.f);
#pragma unroll
    for (int o = 16; o > 0; o >>= 1) sum += __shfl_xor_sync(0xffffffffu, sum, o);
    float ls = m + logf(sum);

    out[(size_t)node * 40 + lane] = v1 - ls;
    if (lane < 8) out[(size_t)node * 40 + 32 + lane] = v2 - ls;
}

// ---------------------------------------------------------------------------
// Launch
// ---------------------------------------------------------------------------
extern "C" void kernel_launch(void* const* d_in, const int* in_sizes, int n_in,
                              void* d_out, int out_size)
{
    const float* x    = (const float*)d_in[0];
    const int*   esrc = (const int*)  d_in[1];
    const int*   edst = (const int*)  d_in[2];
    const float* ew   = (const float*)d_in[3];
    const float* W0   = (const float*)d_in[4];
    const float* b0   = (const float*)d_in[5];
    const float* W1   = (const float*)d_in[6];
    const float* b1   = (const float*)d_in[7];
    const float* Wmid = (const float*)d_in[8];
    const float* bmid = (const float*)d_in[9];
    const float* W15  = (const float*)d_in[10];
    const float* b15  = (const float*)d_in[11];

    const int E = in_sizes[1];
    const int n = in_sizes[0] / 256;
    float* out = (float*)d_out;

    float *z, *h, *accum;
    __half* sup;
    __nv_bfloat16 *wthi, *wtlo, *xhi, *xlo, *hhi, *hlo;
    cudaGetSymbolAddress((void**)&z,     g_z);
    cudaGetSymbolAddress((void**)&h,     g_h);
    cudaGetSymbolAddress((void**)&sup,   g_sup);
    cudaGetSymbolAddress((void**)&accum, g_acc);
    cudaGetSymbolAddress((void**)&wthi,  g_wthi);
    cudaGetSymbolAddress((void**)&wtlo,  g_wtlo);
    cudaGetSymbolAddress((void**)&xhi,   g_xhi);
    cudaGetSymbolAddress((void**)&xlo,   g_xlo);
    cudaGetSymbolAddress((void**)&hhi,   g_hhi);
    cudaGetSymbolAddress((void**)&hlo,   g_hlo);

    cudaFuncSetAttribute(tgemm_kernel<0>, cudaFuncAttributeMaxDynamicSharedMemorySize, SMEMSZ_G);
    cudaFuncSetAttribute(tgemm_kernel<1>, cudaFuncAttributeMaxDynamicSharedMemorySize, SMEMSZ_G);
    cudaFuncSetAttribute(tgemm40_kernel,  cudaFuncAttributeMaxDynamicSharedMemorySize, SMEMSZ_G40);

    const int TB = 256;
    const int gridE = (E + TB - 1) / TB;
    const int gridN = (n + TB - 1) / TB;
    const int gridT = (n + 127) / 128;
    const int gridSpmm = (n + 7) / 8;
    const size_t slab = (size_t)n * 128;

    // 1. CSR build + splits
    zero_deg_kernel<<<gridN, TB>>>(n);
    hist_kernel<<<gridE, TB>>>(edst, E);
    scan_kernel<<<1, 1024>>>(n);
    scatter_kernel<<<gridE, TB>>>(esrc, edst, ew, E);
    split_w_kernel<<<(WT_TOTAL + TB - 1) / TB, TB>>>(W0, W1, Wmid, W15);
    split_x_kernel<<<(n * 256 + TB - 1) / TB, TB>>>(x, n * 256);

    // 2. layer 1
    tgemm_kernel<0><<<gridT, 256, SMEMSZ_G>>>(xhi, xlo, wthi + WOFF_W0, wtlo + WOFF_W0, b0, z, n, 256);
    tgemm_kernel<1><<<gridT, 256, SMEMSZ_G>>>(xhi, xlo, wthi + WOFF_W1, wtlo + WOFF_W1, nullptr, sup, n, 256);
    spmm_relu_res_kernel<<<gridSpmm, 256>>>(sup, b1, z, h, hhi, hlo, n);

    // 3. mid layers
    for (int l = 0; l < 13; l++) {
        tgemm_kernel<1><<<gridT, 256, SMEMSZ_G>>>(hhi + (size_t)l * slab, hlo + (size_t)l * slab,
                                                  wthi + WOFF_MID + (size_t)l * 16384,
                                                  wtlo + WOFF_MID + (size_t)l * 16384,
                                                  nullptr, sup, n, 128);
        spmm_relu_res_kernel<<<gridSpmm, 256>>>(sup, bmid + (size_t)l * 128, h, h,
                                                hhi + (size_t)(l + 1) * slab,
                                                hlo + (size_t)(l + 1) * slab, n);
    }

    // 4. P = X_cat @ W15
    tgemm40_kernel<<<gridT, 256, SMEMSZ_G40>>>(hhi, hlo, wthi + WOFF_W15, wtlo + WOFF_W15, accum, n);

    // 5. out = log_softmax(agg40(P) + b15)
    spmm40_lsm_kernel<<<gridSpmm, 256>>>(accum, b15, out, n);
}